// round 15
// baseline (speedup 1.0000x reference)
#include <cuda_runtime.h>
#include <cuda_bf16.h>

// Problem constants (fixed by reference setup_inputs)
#define BB 1024
#define NN 4096
#define CC 21
#define NTHREADS 256
#define BPB 4                    // batches per block
#define NBLK (BB / BPB)          // 256

// Scratch (__device__ globals are the allowed scratch path)
__device__ float g_partials[NBLK];

__device__ __forceinline__ float sqrt_approx(float x) {
    float r;
    asm("sqrt.approx.f32 %0, %1;" : "=f"(r) : "f"(x));
    return r;
}

__device__ __forceinline__ float point_norm(float x, float y, float z,
                                            float c0, float c1, float c2,
                                            float c3, float c4, float c5) {
    float q = fmaf(x, fmaf(c0, x, fmaf(c3, y, c4 * z)),
               fmaf(y, fmaf(c1, y, c5 * z),
                    c2 * z * z));
    return sqrt_approx(fmaxf(q, 0.0f));
}

// Gram coefficients for batch b: M = (Rp - Rg)^T (Rp - Rg), c3..c5 carry the 2x.
__device__ __forceinline__ void gram_coeffs(const float* __restrict__ pred_q,
                                            const float* __restrict__ gt_q,
                                            int b, float* c6) {
    float Rp[9], Rg[9];
    {
        float x = pred_q[4 * b + 0], y = pred_q[4 * b + 1];
        float z = pred_q[4 * b + 2], w = pred_q[4 * b + 3];
        float x2 = x * x, y2 = y * y, z2 = z * z;
        float xy = x * y, xz = x * z, yz = y * z;
        float wx = w * x, wy = w * y, wz = w * z;
        Rp[0] = 1.0f - 2.0f * (y2 + z2); Rp[1] = 2.0f * (xy - wz); Rp[2] = 2.0f * (xz + wy);
        Rp[3] = 2.0f * (xy + wz); Rp[4] = 1.0f - 2.0f * (x2 + z2); Rp[5] = 2.0f * (yz - wx);
        Rp[6] = 2.0f * (xz - wy); Rp[7] = 2.0f * (yz + wx); Rp[8] = 1.0f - 2.0f * (x2 + y2);
    }
    {
        float x = gt_q[4 * b + 0], y = gt_q[4 * b + 1];
        float z = gt_q[4 * b + 2], w = gt_q[4 * b + 3];
        float x2 = x * x, y2 = y * y, z2 = z * z;
        float xy = x * y, xz = x * z, yz = y * z;
        float wx = w * x, wy = w * y, wz = w * z;
        Rg[0] = 1.0f - 2.0f * (y2 + z2); Rg[1] = 2.0f * (xy - wz); Rg[2] = 2.0f * (xz + wy);
        Rg[3] = 2.0f * (xy + wz); Rg[4] = 1.0f - 2.0f * (x2 + z2); Rg[5] = 2.0f * (yz - wx);
        Rg[6] = 2.0f * (xz - wy); Rg[7] = 2.0f * (yz + wx); Rg[8] = 1.0f - 2.0f * (x2 + y2);
    }
    float d[9];
    #pragma unroll
    for (int i = 0; i < 9; i++) d[i] = Rp[i] - Rg[i];
    c6[0] = d[0]*d[0] + d[3]*d[3] + d[6]*d[6];
    c6[1] = d[1]*d[1] + d[4]*d[4] + d[7]*d[7];
    c6[2] = d[2]*d[2] + d[5]*d[5] + d[8]*d[8];
    c6[3] = 2.0f * (d[0]*d[1] + d[3]*d[4] + d[6]*d[7]);
    c6[4] = 2.0f * (d[0]*d[2] + d[3]*d[5] + d[6]*d[8]);
    c6[5] = 2.0f * (d[1]*d[2] + d[4]*d[5] + d[7]*d[8]);
}

__global__ void __launch_bounds__(NTHREADS)
point_loss_kernel(const float* __restrict__ pred_q,
                  const float* __restrict__ gt_q,
                  const void* __restrict__ cls_raw,
                  const float* __restrict__ bank) {
    const int blk = blockIdx.x;
    const int tid = threadIdx.x;

    __shared__ float sc[BPB][6];
    __shared__ int   s_cidx[BPB];
    __shared__ int   s_is64;
    __shared__ float swarp[NTHREADS / 32];

    // ---- warp 0: dtype detection, then per-lane gram setup ----
    if (tid < 32) {
        // int64 layout (LE): odd int32 words are high halves == 0 (values < 21).
        const int* cls32 = (const int*)cls_raw;
        int all_zero = 1;
        #pragma unroll
        for (int i = tid; i < 64; i += 32)
            if (cls32[2 * i + 1] != 0) all_zero = 0;
        all_zero = __all_sync(0xffffffffu, all_zero);
        if (tid == 0) s_is64 = all_zero;
        __syncwarp();
        // lanes 0..BPB-1: gram coefficients + class index, in parallel
        if (tid < BPB) {
            const int b = blk * BPB + tid;
            float c6[6];
            gram_coeffs(pred_q, gt_q, b, c6);
            #pragma unroll
            for (int i = 0; i < 6; i++) sc[tid][i] = c6[i];
            int cidx;
            if (all_zero) cidx = (int)((const long long*)cls_raw)[b];
            else          cidx = ((const int*)cls_raw)[b];
            s_cidx[tid] = min(max(cidx, 0), CC - 1);
        }
    }
    __syncthreads();

    float acc0 = 0.0f, acc1 = 0.0f, acc2 = 0.0f, acc3 = 0.0f;

    #pragma unroll
    for (int bb = 0; bb < BPB; bb++) {
        const float c0 = sc[bb][0], c1 = sc[bb][1], c2 = sc[bb][2];
        const float c3 = sc[bb][3], c4 = sc[bb][4], c5 = sc[bb][5];
        const float4* __restrict__ base4 =
            (const float4*)(bank + (size_t)s_cidx[bb] * (size_t)(NN * 3));

        // Software-pipelined: 4 iterations x 3 float4 (= 4 points each).
        float4 a = base4[tid * 3 + 0];
        float4 v = base4[tid * 3 + 1];
        float4 w = base4[tid * 3 + 2];

        #pragma unroll
        for (int it = 0; it < (NN / 4) / NTHREADS; ++it) {
            float4 na, nv, nw;
            if (it < (NN / 4) / NTHREADS - 1) {
                int tri = (it + 1) * NTHREADS + tid;
                na = base4[tri * 3 + 0];
                nv = base4[tri * 3 + 1];
                nw = base4[tri * 3 + 2];
            }
            acc0 += point_norm(a.x, a.y, a.z, c0, c1, c2, c3, c4, c5);
            acc1 += point_norm(a.w, v.x, v.y, c0, c1, c2, c3, c4, c5);
            acc2 += point_norm(v.z, v.w, w.x, c0, c1, c2, c3, c4, c5);
            acc3 += point_norm(w.y, w.z, w.w, c0, c1, c2, c3, c4, c5);
            a = na; v = nv; w = nw;
        }
    }

    float acc = (acc0 + acc1) + (acc2 + acc3);

    // ---- block reduce ----
    #pragma unroll
    for (int o = 16; o > 0; o >>= 1)
        acc += __shfl_xor_sync(0xffffffffu, acc, o);
    if ((tid & 31) == 0) swarp[tid >> 5] = acc;
    __syncthreads();
    if (tid == 0) {
        float s = 0.0f;
        #pragma unroll
        for (int i = 0; i < NTHREADS / 32; i++) s += swarp[i];
        g_partials[blk] = s;
    }
}

// Single-warp, barrier-free final reduce: fixed order -> deterministic.
__global__ void __launch_bounds__(32)
reduce_kernel(float* __restrict__ out) {
    const int t = threadIdx.x;
    const float4* p4 = (const float4*)g_partials;  // 64 float4s

    double s = 0.0;
    #pragma unroll
    for (int i = 0; i < NBLK / 4 / 32; i++) {      // 2 independent float4 loads/lane
        float4 v = p4[i * 32 + t];
        s += ((double)v.x + (double)v.y) + ((double)v.z + (double)v.w);
    }
    #pragma unroll
    for (int o = 16; o > 0; o >>= 1)
        s += __shfl_xor_sync(0xffffffffu, s, o);
    if (t == 0)
        out[0] = (float)(s / (double)((long long)BB * NN));
}

extern "C" void kernel_launch(void* const* d_in, const int* in_sizes, int n_in,
                              void* d_out, int out_size) {
    // Resolve inputs by element count (robust to metadata ordering):
    //   pred_q / gt_q : 4096 elems (order of appearance; loss is symmetric in swap)
    //   class_indices : 1024 elems
    //   point_bank    : 258048 elems
    const float* pred_q = nullptr;
    const float* gt_q   = nullptr;
    const void*  cls    = nullptr;
    const float* bank   = nullptr;

    for (int i = 0; i < n_in; i++) {
        int sz = in_sizes[i];
        if (sz == BB) {
            cls = d_in[i];
        } else if (sz == CC * NN * 3) {
            bank = (const float*)d_in[i];
        } else if (sz == BB * 4) {
            if (!pred_q) pred_q = (const float*)d_in[i];
            else         gt_q   = (const float*)d_in[i];
        }
    }
    float* out = (float*)d_out;

    point_loss_kernel<<<NBLK, NTHREADS>>>(pred_q, gt_q, cls, bank);
    reduce_kernel<<<1, 32>>>(out);
}

// round 16
// speedup vs baseline: 1.3008x; 1.3008x over previous
#include <cuda_runtime.h>
#include <cuda_bf16.h>

// Problem constants (fixed by reference setup_inputs)
#define BB 1024
#define NN 4096
#define CC 21
#define NTHREADS 256
#define BPB 2                    // batches per block (512 blocks = measured sweet spot)
#define NBLK (BB / BPB)          // 512

// Scratch (__device__ globals are the allowed scratch path)
__device__ float g_partials[NBLK];
__device__ unsigned int g_count;   // ticket; last block resets it each call

__device__ __forceinline__ float sqrt_approx(float x) {
    float r;
    asm("sqrt.approx.f32 %0, %1;" : "=f"(r) : "f"(x));
    return r;
}

__device__ __forceinline__ float point_norm(float x, float y, float z,
                                            float c0, float c1, float c2,
                                            float c3, float c4, float c5) {
    float q = fmaf(x, fmaf(c0, x, fmaf(c3, y, c4 * z)),
               fmaf(y, fmaf(c1, y, c5 * z),
                    c2 * z * z));
    return sqrt_approx(fmaxf(q, 0.0f));
}

// Gram coefficients for batch b: M = (Rp - Rg)^T (Rp - Rg), c3..c5 carry the 2x.
__device__ __forceinline__ void gram_coeffs(const float* __restrict__ pred_q,
                                            const float* __restrict__ gt_q,
                                            int b, float* c6) {
    float Rp[9], Rg[9];
    {
        float x = pred_q[4 * b + 0], y = pred_q[4 * b + 1];
        float z = pred_q[4 * b + 2], w = pred_q[4 * b + 3];
        float x2 = x * x, y2 = y * y, z2 = z * z;
        float xy = x * y, xz = x * z, yz = y * z;
        float wx = w * x, wy = w * y, wz = w * z;
        Rp[0] = 1.0f - 2.0f * (y2 + z2); Rp[1] = 2.0f * (xy - wz); Rp[2] = 2.0f * (xz + wy);
        Rp[3] = 2.0f * (xy + wz); Rp[4] = 1.0f - 2.0f * (x2 + z2); Rp[5] = 2.0f * (yz - wx);
        Rp[6] = 2.0f * (xz - wy); Rp[7] = 2.0f * (yz + wx); Rp[8] = 1.0f - 2.0f * (x2 + y2);
    }
    {
        float x = gt_q[4 * b + 0], y = gt_q[4 * b + 1];
        float z = gt_q[4 * b + 2], w = gt_q[4 * b + 3];
        float x2 = x * x, y2 = y * y, z2 = z * z;
        float xy = x * y, xz = x * z, yz = y * z;
        float wx = w * x, wy = w * y, wz = w * z;
        Rg[0] = 1.0f - 2.0f * (y2 + z2); Rg[1] = 2.0f * (xy - wz); Rg[2] = 2.0f * (xz + wy);
        Rg[3] = 2.0f * (xy + wz); Rg[4] = 1.0f - 2.0f * (x2 + z2); Rg[5] = 2.0f * (yz - wx);
        Rg[6] = 2.0f * (xz - wy); Rg[7] = 2.0f * (yz + wx); Rg[8] = 1.0f - 2.0f * (x2 + y2);
    }
    float d[9];
    #pragma unroll
    for (int i = 0; i < 9; i++) d[i] = Rp[i] - Rg[i];
    c6[0] = d[0]*d[0] + d[3]*d[3] + d[6]*d[6];
    c6[1] = d[1]*d[1] + d[4]*d[4] + d[7]*d[7];
    c6[2] = d[2]*d[2] + d[5]*d[5] + d[8]*d[8];
    c6[3] = 2.0f * (d[0]*d[1] + d[3]*d[4] + d[6]*d[7]);
    c6[4] = 2.0f * (d[0]*d[2] + d[3]*d[5] + d[6]*d[8]);
    c6[5] = 2.0f * (d[1]*d[2] + d[4]*d[5] + d[7]*d[8]);
}

__global__ void __launch_bounds__(NTHREADS)
point_loss_kernel(const float* __restrict__ pred_q,
                  const float* __restrict__ gt_q,
                  const void* __restrict__ cls_raw,
                  const float* __restrict__ bank,
                  float* __restrict__ out) {
    const int blk = blockIdx.x;
    const int tid = threadIdx.x;

    __shared__ float sc[BPB][6];
    __shared__ int   s_cidx[BPB];
    __shared__ float swarp[NTHREADS / 32];
    __shared__ bool  s_last;

    // ---- warp 0: dtype detection, then per-lane gram setup ----
    if (tid < 32) {
        // int64 layout (LE): odd int32 words are high halves == 0 (values < 21).
        const int* cls32 = (const int*)cls_raw;
        int all_zero = 1;
        #pragma unroll
        for (int i = tid; i < 64; i += 32)
            if (cls32[2 * i + 1] != 0) all_zero = 0;
        all_zero = __all_sync(0xffffffffu, all_zero);
        // lanes 0..BPB-1: gram coefficients + class index, in parallel
        if (tid < BPB) {
            const int b = blk * BPB + tid;
            float c6[6];
            gram_coeffs(pred_q, gt_q, b, c6);
            #pragma unroll
            for (int i = 0; i < 6; i++) sc[tid][i] = c6[i];
            int cidx;
            if (all_zero) cidx = (int)((const long long*)cls_raw)[b];
            else          cidx = ((const int*)cls_raw)[b];
            s_cidx[tid] = min(max(cidx, 0), CC - 1);
        }
    }
    __syncthreads();

    float acc0 = 0.0f, acc1 = 0.0f, acc2 = 0.0f, acc3 = 0.0f;

    #pragma unroll
    for (int bb = 0; bb < BPB; bb++) {
        const float c0 = sc[bb][0], c1 = sc[bb][1], c2 = sc[bb][2];
        const float c3 = sc[bb][3], c4 = sc[bb][4], c5 = sc[bb][5];
        const float4* __restrict__ base4 =
            (const float4*)(bank + (size_t)s_cidx[bb] * (size_t)(NN * 3));

        // Software-pipelined: 4 iterations x 3 float4 (= 4 points each).
        float4 a = base4[tid * 3 + 0];
        float4 v = base4[tid * 3 + 1];
        float4 w = base4[tid * 3 + 2];

        #pragma unroll
        for (int it = 0; it < (NN / 4) / NTHREADS; ++it) {
            float4 na, nv, nw;
            if (it < (NN / 4) / NTHREADS - 1) {
                int tri = (it + 1) * NTHREADS + tid;
                na = base4[tri * 3 + 0];
                nv = base4[tri * 3 + 1];
                nw = base4[tri * 3 + 2];
            }
            acc0 += point_norm(a.x, a.y, a.z, c0, c1, c2, c3, c4, c5);
            acc1 += point_norm(a.w, v.x, v.y, c0, c1, c2, c3, c4, c5);
            acc2 += point_norm(v.z, v.w, w.x, c0, c1, c2, c3, c4, c5);
            acc3 += point_norm(w.y, w.z, w.w, c0, c1, c2, c3, c4, c5);
            a = na; v = nv; w = nw;
        }
    }

    float acc = (acc0 + acc1) + (acc2 + acc3);

    // ---- block reduce ----
    #pragma unroll
    for (int o = 16; o > 0; o >>= 1)
        acc += __shfl_xor_sync(0xffffffffu, acc, o);
    if ((tid & 31) == 0) swarp[tid >> 5] = acc;
    __syncthreads();
    if (tid == 0) {
        float s = 0.0f;
        #pragma unroll
        for (int i = 0; i < NTHREADS / 32; i++) s += swarp[i];
        g_partials[blk] = s;
        __threadfence();
        unsigned int ticket = atomicAdd(&g_count, 1u);
        s_last = (ticket == NBLK - 1);
    }
    __syncthreads();

    // ---- last block, warp 0: deterministic fixed-order final reduce ----
    if (s_last && tid < 32) {
        __threadfence();  // acquire: all g_partials visible
        const float4* p4 = (const float4*)g_partials;  // 128 float4s
        double s = 0.0;
        #pragma unroll
        for (int i = 0; i < NBLK / 4 / 32; i++) {      // 4 float4 loads/lane
            float4 v = p4[i * 32 + tid];
            s += ((double)v.x + (double)v.y) + ((double)v.z + (double)v.w);
        }
        #pragma unroll
        for (int o = 16; o > 0; o >>= 1)
            s += __shfl_xor_sync(0xffffffffu, s, o);
        if (tid == 0) {
            out[0] = (float)(s / (double)((long long)BB * NN));
            g_count = 0;   // reset for next graph replay
        }
    }
}

extern "C" void kernel_launch(void* const* d_in, const int* in_sizes, int n_in,
                              void* d_out, int out_size) {
    // Resolve inputs by element count (robust to metadata ordering):
    //   pred_q / gt_q : 4096 elems (order of appearance; loss is symmetric in swap)
    //   class_indices : 1024 elems
    //   point_bank    : 258048 elems
    const float* pred_q = nullptr;
    const float* gt_q   = nullptr;
    const void*  cls    = nullptr;
    const float* bank   = nullptr;

    for (int i = 0; i < n_in; i++) {
        int sz = in_sizes[i];
        if (sz == BB) {
            cls = d_in[i];
        } else if (sz == CC * NN * 3) {
            bank = (const float*)d_in[i];
        } else if (sz == BB * 4) {
            if (!pred_q) pred_q = (const float*)d_in[i];
            else         gt_q   = (const float*)d_in[i];
        }
    }
    float* out = (float*)d_out;

    point_loss_kernel<<<NBLK, NTHREADS>>>(pred_q, gt_q, cls, bank, out);
}